// round 9
// baseline (speedup 1.0000x reference)
#include <cuda_runtime.h>

// PIF integrate-and-fire, closed form:
//   spikes = clamp(floor(x + 0.5f), 0, 8)   (bit-exact vs the T=8 scan)
//
// HBM-bound streaming pass: 205.5 MB in + 205.5 MB out (irreducible).
// Measured roofline: ~6.2 TB/s for the 50/50 R/W mix (R1-R8 sweep:
// MLP/occ/cache-policy/persistence all invariant at 57.7-58.6us kernel).
//
// R9: sm_100 256-bit accesses (LDG.E.256 / STG.E.256 via ld/st.global.v8.f32).
// Same outstanding bytes/warp as the R6 optimum (2x1KB vs 4x512B), half the
// L1tex wavefronts + LSU slots. Prediction: neutral to -0.5us (final axis).

#define TPB 256
#define VPT8 2                      // 256-bit accesses per thread
#define TILE8 (TPB * VPT8)          // float8-units per block = 512

__device__ __forceinline__ void ld256_cs(const float* __restrict__ p, float* r) {
    asm("ld.global.cs.v8.f32 {%0,%1,%2,%3,%4,%5,%6,%7}, [%8];"
        : "=f"(r[0]), "=f"(r[1]), "=f"(r[2]), "=f"(r[3]),
          "=f"(r[4]), "=f"(r[5]), "=f"(r[6]), "=f"(r[7])
        : "l"(p));
}

__device__ __forceinline__ void st256_cs(float* __restrict__ p, const float* r) {
    asm volatile("st.global.cs.v8.f32 [%0], {%1,%2,%3,%4,%5,%6,%7,%8};"
        :: "l"(p),
           "f"(r[0]), "f"(r[1]), "f"(r[2]), "f"(r[3]),
           "f"(r[4]), "f"(r[5]), "f"(r[6]), "f"(r[7])
        : "memory");
}

__device__ __forceinline__ float pif1(float v) {
    return fminf(fmaxf(floorf(v + 0.5f), 0.0f), 8.0f);
}

// Full tiles only — zero predication, compile-time offsets.
__global__ void __launch_bounds__(TPB) pif_main(const float* __restrict__ x,
                                                float* __restrict__ out) {
    // index in 32-byte (float8) units
    long long base = (long long)blockIdx.x * TILE8 + threadIdx.x;

    float a[8], b[8];
    ld256_cs(x + base * 8, a);                       // 2 independent LDG.256
    ld256_cs(x + (base + TPB) * 8, b);

    float ra[8], rb[8];
    #pragma unroll
    for (int i = 0; i < 8; i++) ra[i] = pif1(a[i]);
    #pragma unroll
    for (int i = 0; i < 8; i++) rb[i] = pif1(b[i]);

    st256_cs(out + base * 8, ra);
    st256_cs(out + (base + TPB) * 8, rb);
}

// Ragged edge (float4 granularity) — not hit for this shape, kept for safety.
__global__ void pif_edge4(const float4* __restrict__ x, float4* __restrict__ out,
                          int start, int n4) {
    int i = start + blockIdx.x * blockDim.x + threadIdx.x;
    if (i < n4) {
        float4 v = __ldcs(x + i);
        float4 r;
        r.x = pif1(v.x); r.y = pif1(v.y); r.z = pif1(v.z); r.w = pif1(v.w);
        __stcs(out + i, r);
    }
}

// Ragged edge (scalar granularity) — not hit for this shape, kept for safety.
__global__ void pif_tail(const float* __restrict__ x, float* __restrict__ out,
                         int start, int n) {
    int i = start + blockIdx.x * blockDim.x + threadIdx.x;
    if (i < n) out[i] = pif1(x[i]);
}

extern "C" void kernel_launch(void* const* d_in, const int* in_sizes, int n_in,
                              void* d_out, int out_size) {
    const float* x = (const float*)d_in[0];
    float* out = (float*)d_out;
    int n = in_sizes[0];

    int n8 = n / 8;                                  // float8 units
    int full_blocks = n8 / TILE8;
    if (full_blocks > 0) {
        pif_main<<<full_blocks, TPB>>>(x, out);
    }
    int done4 = full_blocks * TILE8 * 2;             // in float4 units
    int n4 = n / 4;
    if (done4 < n4) {
        int rem = n4 - done4;
        pif_edge4<<<(rem + TPB - 1) / TPB, TPB>>>((const float4*)x, (float4*)out,
                                                  done4, n4);
    }
    int rem_start = n4 * 4;
    if (rem_start < n) {
        int rem = n - rem_start;
        pif_tail<<<(rem + TPB - 1) / TPB, TPB>>>(x, out, rem_start, rem);
    }
}

// round 10
// speedup vs baseline: 1.0010x; 1.0010x over previous
#include <cuda_runtime.h>

// PIF integrate-and-fire, closed form:
//   spikes = clamp(floor(x + 0.5f), 0, 8)   (bit-exact vs the T=8 scan:
//   v0 = x + 0.5, v at step t is exactly v0 - t in fp32 over the relevant
//   range, so spike count = #{t in [0,8): v0 - t >= 1} = clamp(floor(v0),0,8))
//
// HBM-bound streaming pass: 205.5 MB in + 205.5 MB out (irreducible).
// Measured roofline: ~6.24 TB/s for the 50/50 R/W mix. Full design-space
// sweep (R1-R9): MLP {1,4,8}x128b, .cs/.cg, persistent grid, 2x256b —
// optimum is 2x LDG.256/STG.256 per thread with evict-first hints:
// kernel 57.3us, DRAM 76.3%, occ 77%.
//
// Final config (triple-validated family, fastest variant): flat grid,
// branch-free exact-tile main kernel (n8 = 12544 * 512 exactly -> 1 launch),
// sm_100 256-bit global accesses, .cs both sides.

#define TPB 256
#define VPT8 2                      // 256-bit accesses per thread
#define TILE8 (TPB * VPT8)          // float8-units per block = 512

__device__ __forceinline__ void ld256_cs(const float* __restrict__ p, float* r) {
    asm("ld.global.cs.v8.f32 {%0,%1,%2,%3,%4,%5,%6,%7}, [%8];"
        : "=f"(r[0]), "=f"(r[1]), "=f"(r[2]), "=f"(r[3]),
          "=f"(r[4]), "=f"(r[5]), "=f"(r[6]), "=f"(r[7])
        : "l"(p));
}

__device__ __forceinline__ void st256_cs(float* __restrict__ p, const float* r) {
    asm volatile("st.global.cs.v8.f32 [%0], {%1,%2,%3,%4,%5,%6,%7,%8};"
        :: "l"(p),
           "f"(r[0]), "f"(r[1]), "f"(r[2]), "f"(r[3]),
           "f"(r[4]), "f"(r[5]), "f"(r[6]), "f"(r[7])
        : "memory");
}

__device__ __forceinline__ float pif1(float v) {
    return fminf(fmaxf(floorf(v + 0.5f), 0.0f), 8.0f);
}

// Full tiles only — zero predication, compile-time offsets.
__global__ void __launch_bounds__(TPB) pif_main(const float* __restrict__ x,
                                                float* __restrict__ out) {
    // index in 32-byte (float8) units
    long long base = (long long)blockIdx.x * TILE8 + threadIdx.x;

    float a[8], b[8];
    ld256_cs(x + base * 8, a);                       // 2 independent LDG.256
    ld256_cs(x + (base + TPB) * 8, b);

    float ra[8], rb[8];
    #pragma unroll
    for (int i = 0; i < 8; i++) ra[i] = pif1(a[i]);
    #pragma unroll
    for (int i = 0; i < 8; i++) rb[i] = pif1(b[i]);

    st256_cs(out + base * 8, ra);
    st256_cs(out + (base + TPB) * 8, rb);
}

// Ragged edge (float4 granularity) — not hit for this shape, kept for safety.
__global__ void pif_edge4(const float4* __restrict__ x, float4* __restrict__ out,
                          int start, int n4) {
    int i = start + blockIdx.x * blockDim.x + threadIdx.x;
    if (i < n4) {
        float4 v = __ldcs(x + i);
        float4 r;
        r.x = pif1(v.x); r.y = pif1(v.y); r.z = pif1(v.z); r.w = pif1(v.w);
        __stcs(out + i, r);
    }
}

// Ragged edge (scalar granularity) — not hit for this shape, kept for safety.
__global__ void pif_tail(const float* __restrict__ x, float* __restrict__ out,
                         int start, int n) {
    int i = start + blockIdx.x * blockDim.x + threadIdx.x;
    if (i < n) out[i] = pif1(x[i]);
}

extern "C" void kernel_launch(void* const* d_in, const int* in_sizes, int n_in,
                              void* d_out, int out_size) {
    const float* x = (const float*)d_in[0];
    float* out = (float*)d_out;
    int n = in_sizes[0];

    int n8 = n / 8;                                  // float8 units
    int full_blocks = n8 / TILE8;
    if (full_blocks > 0) {
        pif_main<<<full_blocks, TPB>>>(x, out);
    }
    int done4 = full_blocks * TILE8 * 2;             // in float4 units
    int n4 = n / 4;
    if (done4 < n4) {
        int rem = n4 - done4;
        pif_edge4<<<(rem + TPB - 1) / TPB, TPB>>>((const float4*)x, (float4*)out,
                                                  done4, n4);
    }
    int rem_start = n4 * 4;
    if (rem_start < n) {
        int rem = n - rem_start;
        pif_tail<<<(rem + TPB - 1) / TPB, TPB>>>(x, out, rem_start, rem);
    }
}